// round 2
// baseline (speedup 1.0000x reference)
#include <cuda_runtime.h>
#include <cuda_bf16.h>

// QuantumConv2D analytical collapse:
//   out[b,c,h,w] = cos(theta[9]) * prod_{3x3 patch} cos(x[b,c,h+i,w+j])
//
// Heisenberg-picture derivation:
//   - RY(theta_q), q != 9, commute with Z_9 and cancel.
//   - RY(t9)^dag Z RY(t9) = cos(t9) Z - sin(t9) X
//   - CNOT chain pulls Z_9 back to Z_0...Z_9 ; X_9 invariant.
//   - Product state: <Z_q> = cos(a_q), <X_9> = sin(0) = 0, ancilla factor cos(0)=1.
//
// R2 strategy: one thread per output pixel, no smem, no syncs.
//   184512 threads (721 blocks x 256) -> ~39 warps/SM in one wave.
//   9 independent LDG (MLP=9, L1/L2 hit) + 9 MUFU.COS (__cosf) + product tree.
//   __cosf: 1 instr vs ~20 for accurate cosf; error ~5e-7 for |x|~N(0,1),
//   well under the 1e-3 threshold.

#define IMG_H 64
#define IMG_W 64
#define OUT_H 62
#define OUT_W 62
#define N_OUT (48 * OUT_H * OUT_W)   // 16*3 images * 62*62

__global__ __launch_bounds__(256)
void qconv3x3_coscos_kernel(const float* __restrict__ x,
                            const float* __restrict__ theta,
                            float* __restrict__ out)
{
    const int o = blockIdx.x * 256 + threadIdx.x;
    if (o >= N_OUT) return;

    const int bc  = o / (OUT_H * OUT_W);
    const int rem = o - bc * (OUT_H * OUT_W);
    const int r   = rem / OUT_W;
    const int c   = rem - r * OUT_W;

    const float* p = x + bc * (IMG_H * IMG_W) + r * IMG_W + c;

    // 9 independent loads first (max MLP), then 9 MUFU, then product tree.
    float a0 = p[0],            a1 = p[1],            a2 = p[2];
    float a3 = p[IMG_W],        a4 = p[IMG_W + 1],    a5 = p[IMG_W + 2];
    float a6 = p[2 * IMG_W],    a7 = p[2 * IMG_W + 1], a8 = p[2 * IMG_W + 2];

    float c0 = __cosf(a0), c1 = __cosf(a1), c2 = __cosf(a2);
    float c3 = __cosf(a3), c4 = __cosf(a4), c5 = __cosf(a5);
    float c6 = __cosf(a6), c7 = __cosf(a7), c8 = __cosf(a8);

    const float cT = __cosf(__ldg(&theta[9]));

    // balanced product tree (depth 4)
    float p01 = c0 * c1, p23 = c2 * c3, p45 = c4 * c5, p67 = c6 * c7;
    float p03 = p01 * p23, p47 = p45 * p67;
    float prod = (p03 * p47) * (c8 * cT);

    out[o] = prod;
}

extern "C" void kernel_launch(void* const* d_in, const int* in_sizes, int n_in,
                              void* d_out, int out_size)
{
    const float* x     = (const float*)d_in[0];   // [16,3,64,64] float32
    const float* theta = (const float*)d_in[1];   // [10] float32
    float* out = (float*)d_out;                   // [16,3,62,62] float32

    const int blocks = (N_OUT + 255) / 256;       // 721
    qconv3x3_coscos_kernel<<<blocks, 256>>>(x, theta, out);
}